// round 5
// baseline (speedup 1.0000x reference)
#include <cuda_runtime.h>
#include <cstdint>

#define E_TOT  (256*4096)
#define NNODE  (256*512)
#define DHID   64
#define BNUM   256
#define EPB    4096
#define NPB    512
#define KKEEP  1024
#define KDROP  3072

// chunk-major AB: [batch][chunk 0..127][node 0..511] float4
__device__ float g_AB[(size_t)BNUM * 128 * 512 * 4];
__device__ float g_scores[E_TOT];
__device__ int   g_done1[BNUM];   // A blocks done per batch (target 16)
__device__ int   g_done2[BNUM];   // B blocks done per batch (target 2)

__device__ __forceinline__ unsigned long long pk2(float x, float y) {
    unsigned long long r;
    asm("mov.b64 %0, {%1, %2};" : "=l"(r) : "f"(x), "f"(y));
    return r;
}
__device__ __forceinline__ void fma2(unsigned long long& d,
                                     unsigned long long a, unsigned long long b) {
    asm("fma.rn.f32x2 %0, %1, %2, %0;" : "+l"(d) : "l"(a), "l"(b));
}
__device__ __forceinline__ void rel_inc(int* p) {
    asm volatile("red.release.gpu.global.add.s32 [%0], 1;" :: "l"(p) : "memory");
}
__device__ __forceinline__ void acq_spin(const int* p, int target) {
    int v;
    do {
        asm volatile("ld.acquire.gpu.global.s32 %0, [%1];" : "=r"(v) : "l"(p) : "memory");
        if (v < target) __nanosleep(64);
    } while (v < target);
}

// ---------------------------------------------------------------------------
// Role A: GEMM tile 64 rows x 256 cols (half of Wc). f32x2 FMA.
// Output chunk-major via SMEM staging (aliased over Ws/hs).
// ---------------------------------------------------------------------------
__device__ __forceinline__ void roleA(const float* __restrict__ hmat,
                                      const float* __restrict__ W1,
                                      float* smem, int b, int local) {
    float* Ws = smem;              // [64][256]
    float* hs = smem + 64 * 256;   // [64][68] transposed h
    const int tid  = threadIdx.x;
    const int t    = local >> 1;          // 0..7 row tile within batch
    const int half = local & 1;           // 0 = A-half, 1 = B-half of W1
    const int nboff = t * 64;
    const int rowbase = b * NPB + nboff;

    for (int i = tid; i < 64 * 64; i += 512) {
        int k = i >> 6, o4 = i & 63;
        *(float4*)(Ws + k * 256 + o4 * 4) =
            *(const float4*)(W1 + (size_t)(half * 64 + k) * 256 + o4 * 4);
    }
    for (int i = tid; i < 64 * 16; i += 512) {
        int n = i >> 4, k4 = i & 15;
        float4 v = *(const float4*)(hmat + (size_t)(rowbase + n) * 64 + k4 * 4);
        hs[(k4 * 4 + 0) * 68 + n] = v.x;
        hs[(k4 * 4 + 1) * 68 + n] = v.y;
        hs[(k4 * 4 + 2) * 68 + n] = v.z;
        hs[(k4 * 4 + 3) * 68 + n] = v.w;
    }
    __syncthreads();

    const int w = tid >> 5, l = tid & 31;
    const int r0 = w * 4;                 // 4 rows per thread

    unsigned long long acc[4][4];
    #pragma unroll
    for (int i = 0; i < 4; ++i)
        #pragma unroll
        for (int p = 0; p < 4; ++p) acc[i][p] = 0ull;

    #pragma unroll 4
    for (int k = 0; k < 64; ++k) {
        float4 hv = *(const float4*)(hs + k * 68 + r0);            // warp broadcast
        ulonglong2 b0 = *(const ulonglong2*)(Ws + k * 256 + 4 * l);
        ulonglong2 b1v = *(const ulonglong2*)(Ws + k * 256 + 128 + 4 * l);
        #pragma unroll
        for (int i = 0; i < 4; ++i) {
            float h = (i == 0) ? hv.x : (i == 1) ? hv.y : (i == 2) ? hv.z : hv.w;
            unsigned long long a2 = pk2(h, h);
            fma2(acc[i][0], a2, b0.x); fma2(acc[i][1], a2, b0.y);
            fma2(acc[i][2], a2, b1v.x); fma2(acc[i][3], a2, b1v.y);
        }
    }

    __syncthreads();
    float4* buf = (float4*)smem;   // [64 chunks][65] float4 (aliased)
    #pragma unroll
    for (int i = 0; i < 4; ++i) {
        int node = r0 + i;
        float4 v0, v1;
        *(unsigned long long*)&v0.x = acc[i][0];
        *(unsigned long long*)&v0.z = acc[i][1];
        *(unsigned long long*)&v1.x = acc[i][2];
        *(unsigned long long*)&v1.z = acc[i][3];
        buf[l * 65 + node]        = v0;   // chunk l      (cols 4l..4l+3)
        buf[(32 + l) * 65 + node] = v1;   // chunk 32+l   (cols 128+4l..)
    }
    __syncthreads();
    float4* dst = (float4*)g_AB;
    #pragma unroll
    for (int j = 0; j < 8; ++j) {
        int idx = tid + 512 * j;          // 0..4095
        int cc = idx >> 6, node = idx & 63;
        dst[((size_t)b * 128 + half * 64 + cc) * 512 + nboff + node] = buf[cc * 65 + node];
    }
    __syncthreads();
    if (tid == 0) rel_inc(g_done1 + b);
}

// ---------------------------------------------------------------------------
// Role B: edge scores, 2048 edges, chunk-4 streaming (double-buffered).
// ---------------------------------------------------------------------------
__device__ __forceinline__ void roleB(const float* __restrict__ b1,
                                      const float* __restrict__ W2,
                                      const float* __restrict__ b2p,
                                      const int*   __restrict__ ei,
                                      float* smem, int b, int eh) {
    float* As  = smem;             // [2][2048]
    float* Bs  = smem + 4096;      // [2][2048]
    float* w2s = smem + 8192;      // [256]
    float* b1s = w2s + 256;        // [256]
    const int tid = threadIdx.x;
    const int ebase = b * EPB + eh * 2048;

    if (tid < 64)       *(float4*)(w2s + tid * 4)        = *(const float4*)(W2 + tid * 4);
    else if (tid < 128) *(float4*)(b1s + (tid - 64) * 4) = *(const float4*)(b1 + (tid - 64) * 4);

    int roff[4], coff[4];
    float acc[4];
    #pragma unroll
    for (int i = 0; i < 4; ++i) {
        int e = ebase + tid + i * 512;
        roff[i] = (ei[e]         - b * NPB) * 4;
        coff[i] = (ei[E_TOT + e] - b * NPB) * 4;
        acc[i] = 0.f;
    }

    if (tid == 0) acq_spin(g_done1 + b, 16);
    __syncthreads();

    const float4* gA = (const float4*)g_AB + (size_t)b * 128 * 512;
    float4 ra = gA[tid];                 // chunk 0 (A)
    float4 rb = gA[(size_t)64 * 512 + tid];  // chunk 64 (B)

    for (int c = 0; c < 64; ++c) {
        const int buf = c & 1;
        float4 bv = *(const float4*)(b1s + c * 4);
        float4 wa;
        wa.x = ra.x + bv.x; wa.y = ra.y + bv.y;
        wa.z = ra.z + bv.z; wa.w = ra.w + bv.w;
        *(float4*)(As + buf * 2048 + tid * 4) = wa;
        *(float4*)(Bs + buf * 2048 + tid * 4) = rb;
        __syncthreads();
        if (c + 1 < 64) {
            ra = gA[(size_t)(c + 1)  * 512 + tid];
            rb = gA[(size_t)(c + 65) * 512 + tid];
        }
        const float4 w2v = *(const float4*)(w2s + c * 4);
        const float* Ab = As + buf * 2048;
        const float* Bb = Bs + buf * 2048;
        #pragma unroll
        for (int i = 0; i < 4; ++i) {
            float4 av = *(const float4*)(Ab + roff[i]);
            float4 b4 = *(const float4*)(Bb + coff[i]);
            float s = acc[i];
            s = fmaf(fmaxf(av.x + b4.x, 0.f), w2v.x, s);
            s = fmaf(fmaxf(av.y + b4.y, 0.f), w2v.y, s);
            s = fmaf(fmaxf(av.z + b4.z, 0.f), w2v.z, s);
            s = fmaf(fmaxf(av.w + b4.w, 0.f), w2v.w, s);
            acc[i] = s;
        }
    }
    const float b2v = b2p[0];
    #pragma unroll
    for (int i = 0; i < 4; ++i)
        g_scores[ebase + tid + i * 512] = acc[i] + b2v;
    __syncthreads();
    if (tid == 0) rel_inc(g_done2 + b);
}

// ---------------------------------------------------------------------------
// Role C: bitonic argsort (8 keys/thread, 512 thr) + outputs + SMEM mask +
// fused segment-sum.
// ---------------------------------------------------------------------------
__device__ __forceinline__ void roleC(const int* __restrict__ ei,
                                      float* __restrict__ out,
                                      const float* __restrict__ hmat,
                                      float* smem, int b) {
    unsigned long long* sk = (unsigned long long*)smem;   // [4096] (32 KB)
    float* smask = smem + 8192;                            // [512]
    float* red   = smask + 512;                            // [8][64]
    const int tid = threadIdx.x;

    smask[tid] = 0.f;
    if (tid == 0) acq_spin(g_done2 + b, 2);
    __syncthreads();

    unsigned long long key[8];
    {
        float4 s0 = *(const float4*)(g_scores + b * EPB + tid * 8);
        float4 s1 = *(const float4*)(g_scores + b * EPB + tid * 8 + 4);
        float sv[8] = {s0.x, s0.y, s0.z, s0.w, s1.x, s1.y, s1.z, s1.w};
        #pragma unroll
        for (int r = 0; r < 8; ++r) {
            unsigned int u = __float_as_uint(sv[r]);
            unsigned int enc = (u & 0x80000000u) ? ~u : (u | 0x80000000u);
            key[r] = ((unsigned long long)(~enc) << 32) | (unsigned int)(tid * 8 + r);
        }
    }

    for (int k = 2; k <= 4096; k <<= 1) {
        int j = k >> 1;
        for (; j >= 256; j >>= 1) {          // cross-warp via SMEM
            #pragma unroll
            for (int r = 0; r < 8; ++r) sk[tid * 8 + r] = key[r];
            __syncthreads();
            #pragma unroll
            for (int r = 0; r < 8; ++r) {
                int i = tid * 8 + r;
                unsigned long long pk = sk[i ^ j];
                bool up = ((i & k) == 0);
                bool lo = ((i & j) == 0);
                unsigned long long mn = key[r] < pk ? key[r] : pk;
                unsigned long long mx = key[r] < pk ? pk : key[r];
                key[r] = (lo == up) ? mn : mx;
            }
            __syncthreads();
        }
        for (; j >= 8; j >>= 1) {            // intra-warp via shfl
            int lm = j >> 3;
            #pragma unroll
            for (int r = 0; r < 8; ++r) {
                unsigned long long pk = __shfl_xor_sync(0xffffffffu, key[r], lm);
                int i = tid * 8 + r;
                bool up = ((i & k) == 0);
                bool lo = ((i & j) == 0);
                unsigned long long mn = key[r] < pk ? key[r] : pk;
                unsigned long long mx = key[r] < pk ? pk : key[r];
                key[r] = (lo == up) ? mn : mx;
            }
        }
        for (; j >= 1; j >>= 1) {            // in-thread (j = 4,2,1)
            #pragma unroll
            for (int r = 0; r < 8; ++r) {
                if ((r & j) == 0) {
                    int p = r | j;
                    int i = tid * 8 + r;
                    bool up = ((i & k) == 0);
                    unsigned long long a = key[r], c2 = key[p];
                    unsigned long long mn = a < c2 ? a : c2;
                    unsigned long long mx = a < c2 ? c2 : a;
                    key[r] = up ? mn : mx;
                    key[p] = up ? mx : mn;
                }
            }
        }
    }

    const int ok = BNUM * DHID;
    const int os = ok + BNUM * KKEEP;
    #pragma unroll
    for (int r = 0; r < 8; ++r) {
        int pos = tid * 8 + r;
        unsigned long long kv = key[r];
        unsigned int enc = ~(unsigned int)(kv >> 32);
        unsigned int bits = (enc & 0x80000000u) ? (enc ^ 0x80000000u) : ~enc;
        float s = __uint_as_float(bits);
        int idx = (int)(unsigned int)(kv & 0xFFFFFFFFu);
        if (pos < KKEEP) {
            out[ok + b * KKEEP + pos] = s;
            int g = b * EPB + idx;
            smask[ei[g]         - b * NPB] = 1.f;
            smask[ei[E_TOT + g] - b * NPB] = 1.f;
        } else {
            out[os + b * KDROP + (pos - KKEEP)] = -s;
        }
    }
    __syncthreads();

    // fused segment-sum with SMEM mask
    const int d = tid & 63, q = tid >> 6;   // q 0..7
    const size_t nb = (size_t)b * NPB;
    float s0 = 0.f, s1 = 0.f;
    #pragma unroll 4
    for (int n = q; n < NPB; n += 16) {
        s0 = fmaf(smask[n],     hmat[(nb + n) * 64 + d],     s0);
        s1 = fmaf(smask[n + 8], hmat[(nb + n + 8) * 64 + d], s1);
    }
    red[q * 64 + d] = s0 + s1;
    __syncthreads();
    if (tid < 64) {
        float t = 0.f;
        #pragma unroll
        for (int qq = 0; qq < 8; ++qq) t += red[qq * 64 + tid];
        out[b * 64 + tid] = t;
    }
    if (tid == 0) { g_done1[b] = 0; g_done2[b] = 0; }   // reset for next replay
}

// ---------------------------------------------------------------------------
__global__ void __launch_bounds__(512, 2)
mega(const float* __restrict__ hmat, const float* __restrict__ W1,
     const float* __restrict__ b1,   const float* __restrict__ W2,
     const float* __restrict__ b2,   const int* __restrict__ ei,
     float* __restrict__ out) {
    extern __shared__ float smem[];
    const int b = blockIdx.x / 19;
    const int local = blockIdx.x % 19;
    if (local < 16)      roleA(hmat, W1, smem, b, local);
    else if (local < 18) roleB(b1, W2, b2, ei, smem, b, local - 16);
    else                 roleC(ei, out, hmat, smem, b);
}

// ---------------------------------------------------------------------------
extern "C" void kernel_launch(void* const* d_in, const int* in_sizes, int n_in,
                              void* d_out, int out_size) {
    const float* hmat = (const float*)d_in[0];
    const float* W1   = (const float*)d_in[1];
    const float* b1   = (const float*)d_in[2];
    const float* W2   = (const float*)d_in[3];
    const float* b2   = (const float*)d_in[4];
    const int*   ei   = (const int*)  d_in[5];
    float* out = (float*)d_out;

    const int smem = (64 * 256 + 64 * 68) * 4;   // 82944 B (A role; B/C use less)
    cudaFuncSetAttribute(mega, cudaFuncAttributeMaxDynamicSharedMemorySize, smem);
    mega<<<BNUM * 19, 512, smem>>>(hmat, W1, b1, W2, b2, ei, out);
}

// round 6
// speedup vs baseline: 1.3523x; 1.3523x over previous
#include <cuda_runtime.h>
#include <cstdint>

#define E_TOT  (256*4096)
#define NNODE  (256*512)
#define DHID   64
#define BNUM   256
#define EPB    4096
#define NPB    512
#define KKEEP  1024
#define KDROP  3072

// chunk-major AB: [batch][chunk 0..127][node 0..511] float4
__device__ float g_AB[(size_t)BNUM * 128 * 512 * 4];
__device__ float g_scores[E_TOT];

__device__ __forceinline__ unsigned long long pk2(float x, float y) {
    unsigned long long r;
    asm("mov.b64 %0, {%1, %2};" : "=l"(r) : "f"(x), "f"(y));
    return r;
}
__device__ __forceinline__ void fma2(unsigned long long& d,
                                     unsigned long long a, unsigned long long b) {
    asm("fma.rn.f32x2 %0, %1, %2, %0;" : "+l"(d) : "l"(a), "l"(b));
}

// ---------------------------------------------------------------------------
// K1: AB = h @ Wc. CTA = 64 rows x 256 cols (half), 256 thr, 8x8 thread tile.
// LDS per k-iter per warp: 2 broadcast LDS.128 (h) + 2 contiguous LDS.128 (W)
// -> fma-pipe bound. Output chunk-major via SMEM restage, coalesced STG.128.
// ---------------------------------------------------------------------------
__global__ void __launch_bounds__(256) k1_gemm(const float* __restrict__ hmat,
                                               const float* __restrict__ W1) {
    extern __shared__ float sm1[];
    float* Ws = sm1;              // [64][256]  64 KB
    float* hs = sm1 + 64 * 256;   // [64][68]   transposed h tile
    const int tid  = threadIdx.x;
    const int tile = blockIdx.x >> 1;
    const int half = blockIdx.x & 1;          // 0 = A-half of W1, 1 = B-half
    const int rowbase = tile * 64;
    const int b     = rowbase >> 9;
    const int nboff = rowbase & 511;

    #pragma unroll
    for (int j = 0; j < 16; ++j) {
        int i = tid + j * 256;
        int k = i >> 6, o4 = i & 63;
        *(float4*)(Ws + k * 256 + o4 * 4) =
            *(const float4*)(W1 + (size_t)(half * 64 + k) * 256 + o4 * 4);
    }
    #pragma unroll
    for (int j = 0; j < 4; ++j) {
        int i = tid + j * 256;
        int n = i >> 4, k4 = i & 15;
        float4 v = *(const float4*)(hmat + (size_t)(rowbase + n) * 64 + k4 * 4);
        hs[(k4 * 4 + 0) * 68 + n] = v.x;
        hs[(k4 * 4 + 1) * 68 + n] = v.y;
        hs[(k4 * 4 + 2) * 68 + n] = v.z;
        hs[(k4 * 4 + 3) * 68 + n] = v.w;
    }
    __syncthreads();

    const int w = tid >> 5, l = tid & 31;
    const int r0 = w * 8;          // 8 rows
    const int c0 = l * 8;          // 8 cols

    unsigned long long acc[8][4];
    #pragma unroll
    for (int i = 0; i < 8; ++i)
        #pragma unroll
        for (int p = 0; p < 4; ++p) acc[i][p] = 0ull;

    #pragma unroll 4
    for (int k = 0; k < 64; ++k) {
        float4 h0 = *(const float4*)(hs + k * 68 + r0);       // broadcast
        float4 h1 = *(const float4*)(hs + k * 68 + r0 + 4);   // broadcast
        ulonglong2 w0 = *(const ulonglong2*)(Ws + k * 256 + c0);
        ulonglong2 w1 = *(const ulonglong2*)(Ws + k * 256 + c0 + 4);
        float hv[8] = {h0.x, h0.y, h0.z, h0.w, h1.x, h1.y, h1.z, h1.w};
        #pragma unroll
        for (int i = 0; i < 8; ++i) {
            unsigned long long a2 = pk2(hv[i], hv[i]);
            fma2(acc[i][0], a2, w0.x); fma2(acc[i][1], a2, w0.y);
            fma2(acc[i][2], a2, w1.x); fma2(acc[i][3], a2, w1.y);
        }
    }

    // restage chunk-major: thread covers chunks 2l (cols c0..c0+3), 2l+1
    __syncthreads();
    float4* st = (float4*)sm1;    // [64][65] float4 (aliased, 66.6 KB)
    #pragma unroll
    for (int i = 0; i < 8; ++i) {
        int node = r0 + i;
        float4 v0, v1;
        *(unsigned long long*)&v0.x = acc[i][0];
        *(unsigned long long*)&v0.z = acc[i][1];
        *(unsigned long long*)&v1.x = acc[i][2];
        *(unsigned long long*)&v1.z = acc[i][3];
        st[(2 * l)     * 65 + node] = v0;
        st[(2 * l + 1) * 65 + node] = v1;
    }
    __syncthreads();
    float4* dst = (float4*)g_AB;
    #pragma unroll
    for (int j = 0; j < 16; ++j) {
        int idx = tid + j * 256;              // 0..4095
        int cc = idx >> 6, node = idx & 63;
        dst[((size_t)b * 128 + half * 64 + cc) * 512 + nboff + node] = st[cc * 65 + node];
    }
}

// ---------------------------------------------------------------------------
// K2: edge scores, 2 CTAs/batch, chunk-4 streaming, prefetch depth 2.
// ---------------------------------------------------------------------------
__global__ void __launch_bounds__(512) k2_edges(const float* __restrict__ b1,
                                                const float* __restrict__ W2,
                                                const float* __restrict__ b2p,
                                                const int*   __restrict__ ei) {
    __shared__ float As[2][512 * 4];
    __shared__ float Bs[2][512 * 4];
    __shared__ float w2s[256];
    __shared__ float b1s[256];
    const int tid = threadIdx.x;
    const int b   = blockIdx.x >> 1;
    const int eh  = blockIdx.x & 1;
    const int ebase = b * EPB + eh * 2048;

    if (tid < 64)       *(float4*)(w2s + tid * 4)        = *(const float4*)(W2 + tid * 4);
    else if (tid < 128) *(float4*)(b1s + (tid - 64) * 4) = *(const float4*)(b1 + (tid - 64) * 4);

    int roff[4], coff[4];
    float acc[4];
    #pragma unroll
    for (int i = 0; i < 4; ++i) {
        int e = ebase + tid + i * 512;
        roff[i] = (ei[e]         - b * NPB) * 4;
        coff[i] = (ei[E_TOT + e] - b * NPB) * 4;
        acc[i] = 0.f;
    }

    const float4* gA = (const float4*)g_AB + (size_t)b * 128 * 512;
    float4 ra0 = gA[tid],                     rb0 = gA[(size_t)64 * 512 + tid];
    float4 ra1 = gA[(size_t)1 * 512 + tid],   rb1 = gA[(size_t)65 * 512 + tid];
    __syncthreads();

    for (int c = 0; c < 64; ++c) {
        const int buf = c & 1;
        float4 bv = *(const float4*)(b1s + c * 4);
        float4 wa;
        wa.x = ra0.x + bv.x; wa.y = ra0.y + bv.y;
        wa.z = ra0.z + bv.z; wa.w = ra0.w + bv.w;
        *(float4*)(As[buf] + tid * 4) = wa;
        *(float4*)(Bs[buf] + tid * 4) = rb0;
        __syncthreads();
        ra0 = ra1; rb0 = rb1;
        if (c + 2 < 64) {
            ra1 = gA[(size_t)(c + 2)  * 512 + tid];
            rb1 = gA[(size_t)(c + 66) * 512 + tid];
        }
        const float4 w2v = *(const float4*)(w2s + c * 4);
        const float* Ab = As[buf];
        const float* Bb = Bs[buf];
        #pragma unroll
        for (int i = 0; i < 4; ++i) {
            float4 av = *(const float4*)(Ab + roff[i]);
            float4 b4 = *(const float4*)(Bb + coff[i]);
            float s = acc[i];
            s = fmaf(fmaxf(av.x + b4.x, 0.f), w2v.x, s);
            s = fmaf(fmaxf(av.y + b4.y, 0.f), w2v.y, s);
            s = fmaf(fmaxf(av.z + b4.z, 0.f), w2v.z, s);
            s = fmaf(fmaxf(av.w + b4.w, 0.f), w2v.w, s);
            acc[i] = s;
        }
    }
    const float b2v = b2p[0];
    #pragma unroll
    for (int i = 0; i < 4; ++i)
        g_scores[ebase + tid + i * 512] = acc[i] + b2v;
}

// ---------------------------------------------------------------------------
// K3: bitonic argsort + outputs + SMEM mask + fused segment-sum (k0/k4 gone).
// ---------------------------------------------------------------------------
__global__ void __launch_bounds__(1024) k3_sort(const int* __restrict__ ei,
                                                const float* __restrict__ hmat,
                                                float* __restrict__ out) {
    __shared__ unsigned long long sk[4096];
    __shared__ float smask[512];
    __shared__ float red[16][64];
    const int b = blockIdx.x, tid = threadIdx.x;

    if (tid < 512) smask[tid] = 0.f;

    unsigned long long key[4];
    float4 sc = *(const float4*)(g_scores + b * EPB + tid * 4);
    float sv[4] = {sc.x, sc.y, sc.z, sc.w};
    #pragma unroll
    for (int r = 0; r < 4; ++r) {
        unsigned int u = __float_as_uint(sv[r]);
        unsigned int enc = (u & 0x80000000u) ? ~u : (u | 0x80000000u);
        key[r] = ((unsigned long long)(~enc) << 32) | (unsigned int)(tid * 4 + r);
    }

    for (int k = 2; k <= 4096; k <<= 1) {
        int j = k >> 1;
        for (; j >= 128; j >>= 1) {
            #pragma unroll
            for (int r = 0; r < 4; ++r) sk[tid * 4 + r] = key[r];
            __syncthreads();
            #pragma unroll
            for (int r = 0; r < 4; ++r) {
                int i = tid * 4 + r;
                unsigned long long pk = sk[i ^ j];
                bool up = ((i & k) == 0);
                bool lo = ((i & j) == 0);
                unsigned long long mn = key[r] < pk ? key[r] : pk;
                unsigned long long mx = key[r] < pk ? pk : key[r];
                key[r] = (lo == up) ? mn : mx;
            }
            __syncthreads();
        }
        for (; j >= 4; j >>= 1) {
            int lm = j >> 2;
            #pragma unroll
            for (int r = 0; r < 4; ++r) {
                unsigned long long pk = __shfl_xor_sync(0xffffffffu, key[r], lm);
                int i = tid * 4 + r;
                bool up = ((i & k) == 0);
                bool lo = ((i & j) == 0);
                unsigned long long mn = key[r] < pk ? key[r] : pk;
                unsigned long long mx = key[r] < pk ? pk : key[r];
                key[r] = (lo == up) ? mn : mx;
            }
        }
        if (k >= 4) {
            #pragma unroll
            for (int r = 0; r < 2; ++r) {
                int i = tid * 4 + r;
                bool up = ((i & k) == 0);
                unsigned long long a = key[r], c2 = key[r + 2];
                unsigned long long mn = a < c2 ? a : c2;
                unsigned long long mx = a < c2 ? c2 : a;
                key[r]     = up ? mn : mx;
                key[r + 2] = up ? mx : mn;
            }
        }
        #pragma unroll
        for (int p = 0; p < 2; ++p) {
            int r0 = p * 2;
            int i = tid * 4 + r0;
            bool up = ((i & k) == 0);
            unsigned long long a = key[r0], c2 = key[r0 + 1];
            unsigned long long mn = a < c2 ? a : c2;
            unsigned long long mx = a < c2 ? c2 : a;
            key[r0]     = up ? mn : mx;
            key[r0 + 1] = up ? mx : mn;
        }
    }

    const int ok = BNUM * DHID;
    const int os = ok + BNUM * KKEEP;
    #pragma unroll
    for (int r = 0; r < 4; ++r) {
        int pos = tid * 4 + r;
        unsigned long long kv = key[r];
        unsigned int enc = ~(unsigned int)(kv >> 32);
        unsigned int bits = (enc & 0x80000000u) ? (enc ^ 0x80000000u) : ~enc;
        float s = __uint_as_float(bits);
        int idx = (int)(unsigned int)(kv & 0xFFFFFFFFu);
        if (pos < KKEEP) {
            out[ok + b * KKEEP + pos] = s;
            int g = b * EPB + idx;
            smask[ei[g]         - b * NPB] = 1.f;
            smask[ei[E_TOT + g] - b * NPB] = 1.f;
        } else {
            out[os + b * KDROP + (pos - KKEEP)] = -s;
        }
    }
    __syncthreads();

    // fused segment-sum
    const int d = tid & 63, q = tid >> 6;    // q 0..15
    const size_t nb = (size_t)b * NPB;
    float s = 0.f;
    #pragma unroll 8
    for (int n = q; n < NPB; n += 16)
        s = fmaf(smask[n], hmat[(nb + n) * 64 + d], s);
    red[q][d] = s;
    __syncthreads();
    if (tid < 64) {
        float t = 0.f;
        #pragma unroll
        for (int qq = 0; qq < 16; ++qq) t += red[qq][tid];
        out[b * 64 + tid] = t;
    }
}

// ---------------------------------------------------------------------------
extern "C" void kernel_launch(void* const* d_in, const int* in_sizes, int n_in,
                              void* d_out, int out_size) {
    const float* hmat = (const float*)d_in[0];
    const float* W1   = (const float*)d_in[1];
    const float* b1   = (const float*)d_in[2];
    const float* W2   = (const float*)d_in[3];
    const float* b2   = (const float*)d_in[4];
    const int*   ei   = (const int*)  d_in[5];
    float* out = (float*)d_out;

    const int smem1 = (64 * 256 + 64 * 68) * 4;   // 82944 B -> 2 CTAs/SM
    cudaFuncSetAttribute(k1_gemm, cudaFuncAttributeMaxDynamicSharedMemorySize, smem1);

    k1_gemm<<<4096, 256, smem1>>>(hmat, W1);
    k2_edges<<<BNUM * 2, 512>>>(b1, W2, b2, ei);
    k3_sort<<<BNUM, 1024>>>(ei, hmat, out);
}

// round 7
// speedup vs baseline: 1.4002x; 1.0354x over previous
#include <cuda_runtime.h>
#include <cstdint>

#define E_TOT  (256*4096)
#define NNODE  (256*512)
#define DHID   64
#define BNUM   256
#define EPB    4096
#define NPB    512
#define KKEEP  1024
#define KDROP  3072

// chunk-major AB: [batch][chunk 0..127][node 0..511] float4
__device__ float g_AB[(size_t)BNUM * 128 * 512 * 4];
__device__ float g_scores[E_TOT];

__device__ __forceinline__ unsigned long long pk2(float x, float y) {
    unsigned long long r;
    asm("mov.b64 %0, {%1, %2};" : "=l"(r) : "f"(x), "f"(y));
    return r;
}
__device__ __forceinline__ void fma2(unsigned long long& d,
                                     unsigned long long a, unsigned long long b) {
    asm("fma.rn.f32x2 %0, %1, %2, %0;" : "+l"(d) : "l"(a), "l"(b));
}

// ---------------------------------------------------------------------------
// K1: AB = h @ Wc. CTA = 64 rows x 256 cols (half), 256 thr, 8 rows x 8 cols.
// Cols per lane: [4l..4l+3] and [128+4l..128+4l+3]  -> contiguous lane reads,
// conflict-free 4-phase LDS.128. h: 2 broadcast LDS.128. fma-pipe bound.
// ---------------------------------------------------------------------------
__global__ void __launch_bounds__(256) k1_gemm(const float* __restrict__ hmat,
                                               const float* __restrict__ W1) {
    extern __shared__ float sm1[];
    float* Ws = sm1;              // [64][256]  64 KB
    float* hs = sm1 + 64 * 256;   // [64][68]   transposed h tile
    const int tid  = threadIdx.x;
    const int tile = blockIdx.x >> 1;
    const int half = blockIdx.x & 1;          // 0 = A-half of W1, 1 = B-half
    const int rowbase = tile * 64;
    const int b     = rowbase >> 9;
    const int nboff = rowbase & 511;

    #pragma unroll
    for (int j = 0; j < 16; ++j) {
        int i = tid + j * 256;
        int k = i >> 6, o4 = i & 63;
        *(float4*)(Ws + k * 256 + o4 * 4) =
            *(const float4*)(W1 + (size_t)(half * 64 + k) * 256 + o4 * 4);
    }
    #pragma unroll
    for (int j = 0; j < 4; ++j) {
        int i = tid + j * 256;
        int n = i >> 4, k4 = i & 15;
        float4 v = *(const float4*)(hmat + (size_t)(rowbase + n) * 64 + k4 * 4);
        hs[(k4 * 4 + 0) * 68 + n] = v.x;
        hs[(k4 * 4 + 1) * 68 + n] = v.y;
        hs[(k4 * 4 + 2) * 68 + n] = v.z;
        hs[(k4 * 4 + 3) * 68 + n] = v.w;
    }
    __syncthreads();

    const int w = tid >> 5, l = tid & 31;
    const int r0 = w * 8;          // 8 rows

    unsigned long long acc[8][4];  // [row][pair]: pairs 0,1 = cols 4l..; 2,3 = 128+4l..
    #pragma unroll
    for (int i = 0; i < 8; ++i)
        #pragma unroll
        for (int p = 0; p < 4; ++p) acc[i][p] = 0ull;

    #pragma unroll 4
    for (int k = 0; k < 64; ++k) {
        float4 h0 = *(const float4*)(hs + k * 68 + r0);       // broadcast
        float4 h1 = *(const float4*)(hs + k * 68 + r0 + 4);   // broadcast
        ulonglong2 w0 = *(const ulonglong2*)(Ws + k * 256 + 4 * l);        // conflict-free
        ulonglong2 w1 = *(const ulonglong2*)(Ws + k * 256 + 128 + 4 * l);  // conflict-free
        float hv[8] = {h0.x, h0.y, h0.z, h0.w, h1.x, h1.y, h1.z, h1.w};
        #pragma unroll
        for (int i = 0; i < 8; ++i) {
            unsigned long long a2 = pk2(hv[i], hv[i]);
            fma2(acc[i][0], a2, w0.x); fma2(acc[i][1], a2, w0.y);
            fma2(acc[i][2], a2, w1.x); fma2(acc[i][3], a2, w1.y);
        }
    }

    // restage chunk-major: lane covers chunk l (cols 4l..4l+3) and chunk 32+l
    __syncthreads();
    float4* st = (float4*)sm1;    // [64][65] float4 (aliased, 66.6 KB)
    #pragma unroll
    for (int i = 0; i < 8; ++i) {
        int node = r0 + i;
        float4 v0, v1;
        *(unsigned long long*)&v0.x = acc[i][0];
        *(unsigned long long*)&v0.z = acc[i][1];
        *(unsigned long long*)&v1.x = acc[i][2];
        *(unsigned long long*)&v1.z = acc[i][3];
        st[l * 65 + node]        = v0;   // chunk l
        st[(32 + l) * 65 + node] = v1;   // chunk 32 + l
    }
    __syncthreads();
    float4* dst = (float4*)g_AB;
    #pragma unroll
    for (int j = 0; j < 16; ++j) {
        int idx = tid + j * 256;              // 0..4095
        int cc = idx >> 6, node = idx & 63;
        dst[((size_t)b * 128 + half * 64 + cc) * 512 + nboff + node] = st[cc * 65 + node];
    }
}

// ---------------------------------------------------------------------------
// K2: edge scores, 2 CTAs/batch, chunk-4 streaming, prefetch depth 2.
// ---------------------------------------------------------------------------
__global__ void __launch_bounds__(512) k2_edges(const float* __restrict__ b1,
                                                const float* __restrict__ W2,
                                                const float* __restrict__ b2p,
                                                const int*   __restrict__ ei) {
    __shared__ float As[2][512 * 4];
    __shared__ float Bs[2][512 * 4];
    __shared__ float w2s[256];
    __shared__ float b1s[256];
    const int tid = threadIdx.x;
    const int b   = blockIdx.x >> 1;
    const int eh  = blockIdx.x & 1;
    const int ebase = b * EPB + eh * 2048;

    if (tid < 64)       *(float4*)(w2s + tid * 4)        = *(const float4*)(W2 + tid * 4);
    else if (tid < 128) *(float4*)(b1s + (tid - 64) * 4) = *(const float4*)(b1 + (tid - 64) * 4);

    int roff[4], coff[4];
    float acc[4];
    #pragma unroll
    for (int i = 0; i < 4; ++i) {
        int e = ebase + tid + i * 512;
        roff[i] = (ei[e]         - b * NPB) * 4;
        coff[i] = (ei[E_TOT + e] - b * NPB) * 4;
        acc[i] = 0.f;
    }

    const float4* gA = (const float4*)g_AB + (size_t)b * 128 * 512;
    float4 ra0 = gA[tid],                     rb0 = gA[(size_t)64 * 512 + tid];
    float4 ra1 = gA[(size_t)1 * 512 + tid],   rb1 = gA[(size_t)65 * 512 + tid];
    __syncthreads();

    for (int c = 0; c < 64; ++c) {
        const int buf = c & 1;
        float4 bv = *(const float4*)(b1s + c * 4);
        float4 wa;
        wa.x = ra0.x + bv.x; wa.y = ra0.y + bv.y;
        wa.z = ra0.z + bv.z; wa.w = ra0.w + bv.w;
        *(float4*)(As[buf] + tid * 4) = wa;
        *(float4*)(Bs[buf] + tid * 4) = rb0;
        __syncthreads();
        ra0 = ra1; rb0 = rb1;
        if (c + 2 < 64) {
            ra1 = gA[(size_t)(c + 2)  * 512 + tid];
            rb1 = gA[(size_t)(c + 66) * 512 + tid];
        }
        const float4 w2v = *(const float4*)(w2s + c * 4);
        const float* Ab = As[buf];
        const float* Bb = Bs[buf];
        #pragma unroll
        for (int i = 0; i < 4; ++i) {
            float4 av = *(const float4*)(Ab + roff[i]);
            float4 b4 = *(const float4*)(Bb + coff[i]);
            float s = acc[i];
            s = fmaf(fmaxf(av.x + b4.x, 0.f), w2v.x, s);
            s = fmaf(fmaxf(av.y + b4.y, 0.f), w2v.y, s);
            s = fmaf(fmaxf(av.z + b4.z, 0.f), w2v.z, s);
            s = fmaf(fmaxf(av.w + b4.w, 0.f), w2v.w, s);
            acc[i] = s;
        }
    }
    const float b2v = b2p[0];
    #pragma unroll
    for (int i = 0; i < 4; ++i)
        g_scores[ebase + tid + i * 512] = acc[i] + b2v;
}

// ---------------------------------------------------------------------------
// K3: bitonic argsort + outputs + SMEM mask + fused segment-sum.
// ---------------------------------------------------------------------------
__global__ void __launch_bounds__(1024) k3_sort(const int* __restrict__ ei,
                                                const float* __restrict__ hmat,
                                                float* __restrict__ out) {
    __shared__ unsigned long long sk[4096];
    __shared__ float smask[512];
    __shared__ float red[16][64];
    const int b = blockIdx.x, tid = threadIdx.x;

    if (tid < 512) smask[tid] = 0.f;

    unsigned long long key[4];
    float4 sc = *(const float4*)(g_scores + b * EPB + tid * 4);
    float sv[4] = {sc.x, sc.y, sc.z, sc.w};
    #pragma unroll
    for (int r = 0; r < 4; ++r) {
        unsigned int u = __float_as_uint(sv[r]);
        unsigned int enc = (u & 0x80000000u) ? ~u : (u | 0x80000000u);
        key[r] = ((unsigned long long)(~enc) << 32) | (unsigned int)(tid * 4 + r);
    }

    for (int k = 2; k <= 4096; k <<= 1) {
        int j = k >> 1;
        for (; j >= 128; j >>= 1) {
            #pragma unroll
            for (int r = 0; r < 4; ++r) sk[tid * 4 + r] = key[r];
            __syncthreads();
            #pragma unroll
            for (int r = 0; r < 4; ++r) {
                int i = tid * 4 + r;
                unsigned long long pk = sk[i ^ j];
                bool up = ((i & k) == 0);
                bool lo = ((i & j) == 0);
                unsigned long long mn = key[r] < pk ? key[r] : pk;
                unsigned long long mx = key[r] < pk ? pk : key[r];
                key[r] = (lo == up) ? mn : mx;
            }
            __syncthreads();
        }
        for (; j >= 4; j >>= 1) {
            int lm = j >> 2;
            #pragma unroll
            for (int r = 0; r < 4; ++r) {
                unsigned long long pk = __shfl_xor_sync(0xffffffffu, key[r], lm);
                int i = tid * 4 + r;
                bool up = ((i & k) == 0);
                bool lo = ((i & j) == 0);
                unsigned long long mn = key[r] < pk ? key[r] : pk;
                unsigned long long mx = key[r] < pk ? pk : key[r];
                key[r] = (lo == up) ? mn : mx;
            }
        }
        if (k >= 4) {
            #pragma unroll
            for (int r = 0; r < 2; ++r) {
                int i = tid * 4 + r;
                bool up = ((i & k) == 0);
                unsigned long long a = key[r], c2 = key[r + 2];
                unsigned long long mn = a < c2 ? a : c2;
                unsigned long long mx = a < c2 ? c2 : a;
                key[r]     = up ? mn : mx;
                key[r + 2] = up ? mx : mn;
            }
        }
        #pragma unroll
        for (int p = 0; p < 2; ++p) {
            int r0 = p * 2;
            int i = tid * 4 + r0;
            bool up = ((i & k) == 0);
            unsigned long long a = key[r0], c2 = key[r0 + 1];
            unsigned long long mn = a < c2 ? a : c2;
            unsigned long long mx = a < c2 ? c2 : a;
            key[r0]     = up ? mn : mx;
            key[r0 + 1] = up ? mx : mn;
        }
    }

    const int ok = BNUM * DHID;
    const int os = ok + BNUM * KKEEP;
    #pragma unroll
    for (int r = 0; r < 4; ++r) {
        int pos = tid * 4 + r;
        unsigned long long kv = key[r];
        unsigned int enc = ~(unsigned int)(kv >> 32);
        unsigned int bits = (enc & 0x80000000u) ? (enc ^ 0x80000000u) : ~enc;
        float s = __uint_as_float(bits);
        int idx = (int)(unsigned int)(kv & 0xFFFFFFFFu);
        if (pos < KKEEP) {
            out[ok + b * KKEEP + pos] = s;
            int g = b * EPB + idx;
            smask[ei[g]         - b * NPB] = 1.f;
            smask[ei[E_TOT + g] - b * NPB] = 1.f;
        } else {
            out[os + b * KDROP + (pos - KKEEP)] = -s;
        }
    }
    __syncthreads();

    // fused segment-sum
    const int d = tid & 63, q = tid >> 6;    // q 0..15
    const size_t nb = (size_t)b * NPB;
    float s = 0.f;
    #pragma unroll 8
    for (int n = q; n < NPB; n += 16)
        s = fmaf(smask[n], hmat[(nb + n) * 64 + d], s);
    red[q][d] = s;
    __syncthreads();
    if (tid < 64) {
        float t = 0.f;
        #pragma unroll
        for (int qq = 0; qq < 16; ++qq) t += red[qq][tid];
        out[b * 64 + tid] = t;
    }
}

// ---------------------------------------------------------------------------
extern "C" void kernel_launch(void* const* d_in, const int* in_sizes, int n_in,
                              void* d_out, int out_size) {
    const float* hmat = (const float*)d_in[0];
    const float* W1   = (const float*)d_in[1];
    const float* b1   = (const float*)d_in[2];
    const float* W2   = (const float*)d_in[3];
    const float* b2   = (const float*)d_in[4];
    const int*   ei   = (const int*)  d_in[5];
    float* out = (float*)d_out;

    const int smem1 = (64 * 256 + 64 * 68) * 4;   // 82944 B -> 2 CTAs/SM
    cudaFuncSetAttribute(k1_gemm, cudaFuncAttributeMaxDynamicSharedMemorySize, smem1);

    k1_gemm<<<4096, 256, smem1>>>(hmat, W1);
    k2_edges<<<BNUM * 2, 512>>>(b1, W2, b2, ei);
    k3_sort<<<BNUM, 1024>>>(ei, hmat, out);
}